// round 11
// baseline (speedup 1.0000x reference)
#include <cuda_runtime.h>
#include <cuda_bf16.h>
#include <cstdint>

typedef unsigned long long ull;

#define NSEQ 480
#define TLEN 200
#define CH   64
#define HID  128
#define G4   512
#define NROW (NSEQ * TLEN)   // 96000

// ---------------- device scratch ----------------
__device__ __nv_bfloat16 g_xh[NROW * CH];    // x hi split, [t*480+seq][c]
__device__ __nv_bfloat16 g_xl[NROW * CH];    // x lo split
__device__ __nv_bfloat16 g_Wh[G4 * CH];      // W_ih hi split, [g][c]
__device__ __nv_bfloat16 g_Wl[G4 * CH];      // W_ih lo split
__device__ __nv_bfloat16 g_WhhHi[G4 * HID];  // W_hh hi split, [g][k]
__device__ __nv_bfloat16 g_WhhLo[G4 * HID];  // W_hh lo split
__device__ float g_xg[NROW * G4];            // input gates [t*480+seq][g]
__device__ float g_bias[G4];

// ---------------- helpers ----------------
__device__ __forceinline__ float tanh_t(float x) {
    float t; asm("tanh.approx.f32 %0, %1;" : "=f"(t) : "f"(x)); return t;
}
__device__ __forceinline__ uint32_t smem_u32(const void* p) {
    uint32_t a;
    asm("{ .reg .u64 t; cvta.to.shared.u64 t, %1; cvt.u32.u64 %0, t; }" : "=r"(a) : "l"(p));
    return a;
}
__device__ __forceinline__ void mma16816(float* d, const uint32_t* a, uint32_t b0, uint32_t b1) {
    asm volatile(
        "mma.sync.aligned.m16n8k16.row.col.f32.bf16.bf16.f32 "
        "{%0,%1,%2,%3}, {%4,%5,%6,%7}, {%8,%9}, {%0,%1,%2,%3};"
        : "+f"(d[0]), "+f"(d[1]), "+f"(d[2]), "+f"(d[3])
        : "r"(a[0]), "r"(a[1]), "r"(a[2]), "r"(a[3]), "r"(b0), "r"(b1));
}

// ---------------- prep: bf16 splits + bias fold ----------------
__global__ void __launch_bounds__(256) prep_kernel(
    const float* __restrict__ Wih, const float* __restrict__ Whh,
    const float* __restrict__ bih, const float* __restrict__ bhh)
{
    int idx = blockIdx.x * 256 + threadIdx.x;
    if (idx < G4 * HID) {
        float w = Whh[idx];
        __nv_bfloat16 hi = __float2bfloat16(w);
        g_WhhHi[idx] = hi;
        g_WhhLo[idx] = __float2bfloat16(w - __bfloat162float(hi));
    }
    if (idx < G4 * CH) {
        float w = Wih[idx];
        __nv_bfloat16 hi = __float2bfloat16(w);
        g_Wh[idx] = hi;
        g_Wl[idx] = __float2bfloat16(w - __bfloat162float(hi));
    }
    if (idx < G4) g_bias[idx] = bih[idx] + bhh[idx];
}

// ---------------- transpose + bf16 split ----------------
__global__ void __launch_bounds__(256) transp_kernel(const float* __restrict__ x)
{
    __shared__ float tile[64 * 30];
    int t = blockIdx.x, b = blockIdx.y;
    for (int idx = threadIdx.x; idx < 64 * 30; idx += 256) {
        int c = idx / 30, p = idx - c * 30;
        tile[idx] = x[(b * 64 + c) * 6000 + t * 30 + p];
    }
    __syncthreads();
    for (int idx = threadIdx.x; idx < 64 * 30; idx += 256) {
        int p = idx >> 6, c = idx & 63;
        float v = tile[c * 30 + p];
        __nv_bfloat16 hi = __float2bfloat16(v);
        int o = (t * NSEQ + b * 30 + p) * 64 + c;
        g_xh[o] = hi;
        g_xl[o] = __float2bfloat16(v - __bfloat162float(hi));
    }
}

// ---------------- HMMA GEMM: xg = split3(x @ Wih^T) + bias (R9, unchanged) ----------------
#define HG_B0   36864
#define HG_BIAS 73728
#define HG_SMEM 74240

__global__ void __launch_bounds__(256) hgemm_kernel()
{
    extern __shared__ char sm[];
    int tid = threadIdx.x, w = tid >> 5, l = tid & 31;
    int row0 = blockIdx.x * 128, col0 = blockIdx.y * 128;

    for (int i = tid; i < 4096; i += 256) {
        int isB = i >> 11;
        int j = i & 2047;
        int arr = j >> 10, rem = j & 1023, row = rem >> 3, ch = rem & 7;
        const uint4* src;
        size_t gidx;
        if (!isB) {
            src = arr ? (const uint4*)g_xl : (const uint4*)g_xh;
            gidx = (size_t)(row0 + row) * 8 + ch;
        } else {
            src = arr ? (const uint4*)g_Wl : (const uint4*)g_Wh;
            gidx = (size_t)(col0 + row) * 8 + ch;
        }
        *(uint4*)(sm + isB * 36864 + arr * 18432 + row * 144 + ch * 16) = src[gidx];
    }
    if (tid < 128) ((float*)(sm + HG_BIAS))[tid] = g_bias[col0 + tid];
    __syncthreads();

    int lr = l >> 2;
    int lc = (l & 3) * 2;

    float acc[16][4];
#pragma unroll
    for (int nf = 0; nf < 16; nf++)
#pragma unroll
        for (int j = 0; j < 4; j++) acc[nf][j] = 0.f;

#pragma unroll
    for (int kf = 0; kf < 4; kf++) {
        int aoff = (w * 16 + lr) * 144 + (kf * 16 + lc) * 2;
        uint32_t ah[4], al[4];
        ah[0] = *(const uint32_t*)(sm + aoff);
        ah[1] = *(const uint32_t*)(sm + aoff + 8 * 144);
        ah[2] = *(const uint32_t*)(sm + aoff + 16);
        ah[3] = *(const uint32_t*)(sm + aoff + 8 * 144 + 16);
        al[0] = *(const uint32_t*)(sm + 18432 + aoff);
        al[1] = *(const uint32_t*)(sm + 18432 + aoff + 8 * 144);
        al[2] = *(const uint32_t*)(sm + 18432 + aoff + 16);
        al[3] = *(const uint32_t*)(sm + 18432 + aoff + 8 * 144 + 16);
#pragma unroll
        for (int nf = 0; nf < 16; nf++) {
            int boff = HG_B0 + (nf * 8 + lr) * 144 + (kf * 16 + lc) * 2;
            uint32_t bh0 = *(const uint32_t*)(sm + boff);
            uint32_t bh1 = *(const uint32_t*)(sm + boff + 16);
            uint32_t bl0 = *(const uint32_t*)(sm + boff + 18432);
            uint32_t bl1 = *(const uint32_t*)(sm + boff + 18432 + 16);
            mma16816(acc[nf], ah, bh0, bh1);
            mma16816(acc[nf], al, bh0, bh1);
            mma16816(acc[nf], ah, bl0, bl1);
        }
    }

    const float* bs = (const float*)(sm + HG_BIAS);
    int rgA = row0 + w * 16 + lr;
#pragma unroll
    for (int nf = 0; nf < 16; nf++) {
        float b0 = bs[nf * 8 + lc], b1 = bs[nf * 8 + lc + 1];
        size_t cA = (size_t)rgA * 512 + col0 + nf * 8 + lc;
        *(float2*)&g_xg[cA] = make_float2(acc[nf][0] + b0, acc[nf][1] + b1);
        *(float2*)&g_xg[cA + 8 * 512] = make_float2(acc[nf][2] + b0, acc[nf][3] + b1);
    }
}

// ---------------- persistent LSTM via HMMA, gate-local warps, 1 bar/step ----------------
// 120 CTAs x 256 threads (8 warps). 4 real seqs (padded to N=8).
// Warp w m-frags: mf = gate; rows mf*128 + w*16 + [0,16). Full K in-warp ->
// lane (l&3)<2 owns complete gates for 4 (r,s) pairs; activations in-register.
// smem:
#define L2_WLO 0                       // WhhLo padded: 512 rows x 272 B = 139264
#define L2_XB  139264                  // xg double buf: 2 x 4x520 floats = 16640
#define L2_HB  155904                  // h bf16 hi/lo, 2 bufs x (8x272 hi + 8x272 lo) = 8704
#define L2_HF  164608                  // h fp32 [128][4] = 2048
#define L2_TOTAL 166656

__global__ void __launch_bounds__(256) lstm3_kernel(
    const float* __restrict__ Wfc, const float* __restrict__ bfc,
    float* __restrict__ out)
{
    extern __shared__ char sm[];
    int tid = threadIdx.x, w = tid >> 5, l = tid & 31;
    int s0 = blockIdx.x * 4;
    uint32_t smb = smem_u32(sm);

    // stage WhhLo into 272-B padded rows
    {
        const uint32_t* wlo = (const uint32_t*)g_WhhLo;  // [512][64] u32
        for (int i = tid; i < 512 * 64; i += 256) {
            int row = i >> 6, cp = i & 63;
            *(uint32_t*)(sm + L2_WLO + row * 272 + cp * 4) = wlo[row * 64 + cp];
        }
    }
    // zero h buffers (padded seq cols stay zero forever)
    for (int i = tid; i < 8704 / 4; i += 256) ((uint32_t*)(sm + L2_HB))[i] = 0;
    // preload xb t=0 (buffer 0)
    const float4* xg4 = (const float4*)g_xg;
    for (int i = tid; i < 512; i += 256) {
        int s = i >> 7, g4i = i & 127;
        *(float4*)(sm + L2_XB + (s * 520 + g4i * 4) * 4) = xg4[(size_t)(s0 + s) * 128 + g4i];
    }

    // WhhHi fragments -> registers: WH[gate][kf][4], rows gate*128 + w*16 + ...
    uint32_t WH[4][8][4];
    {
        const uint32_t* whi = (const uint32_t*)g_WhhHi;  // [512][64] u32
        int lr = l >> 2, lc = l & 3;
#pragma unroll
        for (int mf = 0; mf < 4; mf++)
#pragma unroll
            for (int kf = 0; kf < 8; kf++) {
                int row = mf * 128 + w * 16 + lr;
                int kc = kf * 8 + lc;
                WH[mf][kf][0] = whi[row * 64 + kc];
                WH[mf][kf][1] = whi[(row + 8) * 64 + kc];
                WH[mf][kf][2] = whi[row * 64 + kc + 4];
                WH[mf][kf][3] = whi[(row + 8) * 64 + kc + 4];
            }
    }
    __syncthreads();

    // ldmatrix lane base for WhhLo A-frags (row base per mf: mf*128 + w*16)
    int lm = l >> 3, lr8 = l & 7;
    uint32_t wloBase = smb + L2_WLO
        + (uint32_t)((w * 16 + (lm & 1) * 8 + lr8) * 272 + ((lm >> 1) * 8) * 2);
    // B-frag lane base (h hi, buffer 0)
    uint32_t hbA = smb + L2_HB + (uint32_t)((l >> 2) * 272 + (l & 3) * 4);

    // xb prefetch mapping
    int rC = tid & 127, sB = tid >> 7;

    // activation ownership (lanes with (l&3)<2)
    bool act = (l & 3) < 2;
    int r1 = w * 16 + (l >> 2);
    int sA = (l & 3) * 2;
    float cs[4] = {0.f, 0.f, 0.f, 0.f};

#pragma unroll 1
    for (int t = 0; t < TLEN; t++) {
        bool pf = (t + 1 < TLEN);
        float4 nx0, nx1;
        if (pf) {
            nx0 = xg4[(size_t)((t + 1) * NSEQ + s0 + sB) * 128 + rC];
            nx1 = xg4[(size_t)((t + 1) * NSEQ + s0 + sB + 2) * 128 + rC];
        }

        uint32_t hcur = hbA + (t & 1) * 4352;
        float acc[4][4];
#pragma unroll
        for (int mf = 0; mf < 4; mf++) {
            acc[mf][0] = 0.f; acc[mf][1] = 0.f; acc[mf][2] = 0.f; acc[mf][3] = 0.f;
        }

#pragma unroll
        for (int kf = 0; kf < 8; kf++) {
            uint32_t bh0, bh1, bl0, bl1;
            uint32_t ka = hcur + kf * 32;
            asm volatile("ld.shared.b32 %0, [%1];" : "=r"(bh0) : "r"(ka));
            asm volatile("ld.shared.b32 %0, [%1];" : "=r"(bh1) : "r"(ka + 16));
            asm volatile("ld.shared.b32 %0, [%1];" : "=r"(bl0) : "r"(ka + 2176));
            asm volatile("ld.shared.b32 %0, [%1];" : "=r"(bl1) : "r"(ka + 2192));
#pragma unroll
            for (int mf = 0; mf < 4; mf++) {
                uint32_t wl0, wl1, wl2, wl3;
                uint32_t la = wloBase + mf * (128 * 272) + kf * 32;
                asm volatile("ldmatrix.sync.aligned.m8n8.x4.shared.b16 {%0,%1,%2,%3}, [%4];"
                    : "=r"(wl0), "=r"(wl1), "=r"(wl2), "=r"(wl3) : "r"(la));
                uint32_t wl[4] = {wl0, wl1, wl2, wl3};
                mma16816(acc[mf], WH[mf][kf], bh0, bh1);
                mma16816(acc[mf], WH[mf][kf], bl0, bl1);
                mma16816(acc[mf], wl, bh0, bh1);
            }
        }

        // store next xb buffer
        if (pf) {
            float* xd = (float*)(sm + L2_XB + ((t + 1) & 1) * 8320);
            *(float4*)&xd[sB * 520 + rC * 4] = nx0;
            *(float4*)&xd[(sB + 2) * 520 + rC * 4] = nx1;
        }

        // in-lane activations: lane owns gates i,f,g,o = acc[0..3][j] for
        // (r = r1 + 8*(j>>1), s = sA + (j&1))
        if (act) {
            const float* xbc = (const float*)(sm + L2_XB + (t & 1) * 8320);
            char* hn = sm + L2_HB + ((t + 1) & 1) * 4352;
            float* hf = (float*)(sm + L2_HF);
#pragma unroll
            for (int j = 0; j < 4; j++) {
                int rr = r1 + (j >> 1) * 8;
                int ss = sA + (j & 1);
                float gi = acc[0][j] + xbc[ss * 520 + rr];
                float gf = acc[1][j] + xbc[ss * 520 + 128 + rr];
                float gg = acc[2][j] + xbc[ss * 520 + 256 + rr];
                float go = acc[3][j] + xbc[ss * 520 + 384 + rr];
                float i_ = 0.5f * tanh_t(0.5f * gi) + 0.5f;
                float f_ = 0.5f * tanh_t(0.5f * gf) + 0.5f;
                float o_ = 0.5f * tanh_t(0.5f * go) + 0.5f;
                float g_ = tanh_t(gg);
                cs[j] = f_ * cs[j] + i_ * g_;
                float h = o_ * tanh_t(cs[j]);
                __nv_bfloat16 hi = __float2bfloat16(h);
                float lo = h - __bfloat162float(hi);
                *(__nv_bfloat16*)(hn + ss * 272 + rr * 2) = hi;
                *(__nv_bfloat16*)(hn + 2176 + ss * 272 + rr * 2) = __float2bfloat16(lo);
                if (t == TLEN - 1) hf[rr * 4 + ss] = h;
            }
        }
        __syncthreads();
    }

    // ---- FC epilogue: reuse WLO region for W_fc^T ----
    float* wfs = (float*)sm;
    for (int idx = tid; idx < CH * HID; idx += 256) {
        int c = idx >> 7, j = idx & 127;
        wfs[j * 64 + c] = Wfc[idx];
    }
    __syncthreads();
    {
        int c = tid & 63, s = tid >> 6;
        float accf = bfc[c];
        const float* hf = (const float*)(sm + L2_HF);
#pragma unroll 8
        for (int j = 0; j < HID; j++)
            accf += hf[j * 4 + s] * wfs[j * 64 + c];
        out[(s0 + s) * 64 + c] = accf;
    }
}

// ---------------- launch ----------------
extern "C" void kernel_launch(void* const* d_in, const int* in_sizes, int n_in,
                              void* d_out, int out_size)
{
    const float* x   = (const float*)d_in[0];
    const float* Wih = (const float*)d_in[1];
    const float* Whh = (const float*)d_in[2];
    const float* bih = (const float*)d_in[3];
    const float* bhh = (const float*)d_in[4];
    const float* Wfc = (const float*)d_in[5];
    const float* bfc = (const float*)d_in[6];
    float* out = (float*)d_out;

    cudaFuncSetAttribute(hgemm_kernel, cudaFuncAttributeMaxDynamicSharedMemorySize, HG_SMEM);
    cudaFuncSetAttribute(lstm3_kernel, cudaFuncAttributeMaxDynamicSharedMemorySize, L2_TOTAL);

    prep_kernel<<<256, 256>>>(Wih, Whh, bih, bhh);
    transp_kernel<<<dim3(TLEN, 16), 256>>>(x);
    hgemm_kernel<<<dim3(NROW / 128, 4), 256, HG_SMEM>>>();
    lstm3_kernel<<<120, 256, L2_TOTAL>>>(Wfc, bfc, out);
}

// round 12
// speedup vs baseline: 1.3040x; 1.3040x over previous
#include <cuda_runtime.h>
#include <cuda_bf16.h>
#include <cstdint>

typedef unsigned long long ull;

#define NSEQ 480
#define TLEN 200
#define CH   64
#define HID  128
#define G4   512
#define NROW (NSEQ * TLEN)   // 96000

// ---------------- device scratch ----------------
__device__ __nv_bfloat16 g_xh[NROW * CH];    // x hi split, [t*480+seq][c]
__device__ __nv_bfloat16 g_xl[NROW * CH];    // x lo split
__device__ __nv_bfloat16 g_Wh[G4 * CH];      // W_ih hi split, [g][c]
__device__ __nv_bfloat16 g_Wl[G4 * CH];      // W_ih lo split
__device__ __nv_bfloat16 g_WhhHi[G4 * HID];  // W_hh hi split, [g][k]
__device__ __nv_bfloat16 g_WhhLo[G4 * HID];  // W_hh lo split
__device__ float g_xg[NROW * G4];            // input gates [t*480+seq][g]
__device__ float g_bias[G4];

// ---------------- helpers ----------------
__device__ __forceinline__ float tanh_t(float x) {
    float t; asm("tanh.approx.f32 %0, %1;" : "=f"(t) : "f"(x)); return t;
}
__device__ __forceinline__ uint32_t smem_u32(const void* p) {
    uint32_t a;
    asm("{ .reg .u64 t; cvta.to.shared.u64 t, %1; cvt.u32.u64 %0, t; }" : "=r"(a) : "l"(p));
    return a;
}
__device__ __forceinline__ void mma16816(float* d, const uint32_t* a, uint32_t b0, uint32_t b1) {
    asm volatile(
        "mma.sync.aligned.m16n8k16.row.col.f32.bf16.bf16.f32 "
        "{%0,%1,%2,%3}, {%4,%5,%6,%7}, {%8,%9}, {%0,%1,%2,%3};"
        : "+f"(d[0]), "+f"(d[1]), "+f"(d[2]), "+f"(d[3])
        : "r"(a[0]), "r"(a[1]), "r"(a[2]), "r"(a[3]), "r"(b0), "r"(b1));
}

// ---------------- prep: bf16 splits + bias fold ----------------
__global__ void __launch_bounds__(256) prep_kernel(
    const float* __restrict__ Wih, const float* __restrict__ Whh,
    const float* __restrict__ bih, const float* __restrict__ bhh)
{
    int idx = blockIdx.x * 256 + threadIdx.x;
    if (idx < G4 * HID) {
        float w = Whh[idx];
        __nv_bfloat16 hi = __float2bfloat16(w);
        g_WhhHi[idx] = hi;
        g_WhhLo[idx] = __float2bfloat16(w - __bfloat162float(hi));
    }
    if (idx < G4 * CH) {
        float w = Wih[idx];
        __nv_bfloat16 hi = __float2bfloat16(w);
        g_Wh[idx] = hi;
        g_Wl[idx] = __float2bfloat16(w - __bfloat162float(hi));
    }
    if (idx < G4) g_bias[idx] = bih[idx] + bhh[idx];
}

// ---------------- transpose + bf16 split ----------------
__global__ void __launch_bounds__(256) transp_kernel(const float* __restrict__ x)
{
    __shared__ float tile[64 * 30];
    int t = blockIdx.x, b = blockIdx.y;
    for (int idx = threadIdx.x; idx < 64 * 30; idx += 256) {
        int c = idx / 30, p = idx - c * 30;
        tile[idx] = x[(b * 64 + c) * 6000 + t * 30 + p];
    }
    __syncthreads();
    for (int idx = threadIdx.x; idx < 64 * 30; idx += 256) {
        int p = idx >> 6, c = idx & 63;
        float v = tile[c * 30 + p];
        __nv_bfloat16 hi = __float2bfloat16(v);
        int o = (t * NSEQ + b * 30 + p) * 64 + c;
        g_xh[o] = hi;
        g_xl[o] = __float2bfloat16(v - __bfloat162float(hi));
    }
}

// ---------------- HMMA GEMM: xg = split3(x @ Wih^T) + bias (R9, unchanged) ----------------
#define HG_B0   36864
#define HG_BIAS 73728
#define HG_SMEM 74240

__global__ void __launch_bounds__(256) hgemm_kernel()
{
    extern __shared__ char sm[];
    int tid = threadIdx.x, w = tid >> 5, l = tid & 31;
    int row0 = blockIdx.x * 128, col0 = blockIdx.y * 128;

    for (int i = tid; i < 4096; i += 256) {
        int isB = i >> 11;
        int j = i & 2047;
        int arr = j >> 10, rem = j & 1023, row = rem >> 3, ch = rem & 7;
        const uint4* src;
        size_t gidx;
        if (!isB) {
            src = arr ? (const uint4*)g_xl : (const uint4*)g_xh;
            gidx = (size_t)(row0 + row) * 8 + ch;
        } else {
            src = arr ? (const uint4*)g_Wl : (const uint4*)g_Wh;
            gidx = (size_t)(col0 + row) * 8 + ch;
        }
        *(uint4*)(sm + isB * 36864 + arr * 18432 + row * 144 + ch * 16) = src[gidx];
    }
    if (tid < 128) ((float*)(sm + HG_BIAS))[tid] = g_bias[col0 + tid];
    __syncthreads();

    int lr = l >> 2;
    int lc = (l & 3) * 2;

    float acc[16][4];
#pragma unroll
    for (int nf = 0; nf < 16; nf++)
#pragma unroll
        for (int j = 0; j < 4; j++) acc[nf][j] = 0.f;

#pragma unroll
    for (int kf = 0; kf < 4; kf++) {
        int aoff = (w * 16 + lr) * 144 + (kf * 16 + lc) * 2;
        uint32_t ah[4], al[4];
        ah[0] = *(const uint32_t*)(sm + aoff);
        ah[1] = *(const uint32_t*)(sm + aoff + 8 * 144);
        ah[2] = *(const uint32_t*)(sm + aoff + 16);
        ah[3] = *(const uint32_t*)(sm + aoff + 8 * 144 + 16);
        al[0] = *(const uint32_t*)(sm + 18432 + aoff);
        al[1] = *(const uint32_t*)(sm + 18432 + aoff + 8 * 144);
        al[2] = *(const uint32_t*)(sm + 18432 + aoff + 16);
        al[3] = *(const uint32_t*)(sm + 18432 + aoff + 8 * 144 + 16);
#pragma unroll
        for (int nf = 0; nf < 16; nf++) {
            int boff = HG_B0 + (nf * 8 + lr) * 144 + (kf * 16 + lc) * 2;
            uint32_t bh0 = *(const uint32_t*)(sm + boff);
            uint32_t bh1 = *(const uint32_t*)(sm + boff + 16);
            uint32_t bl0 = *(const uint32_t*)(sm + boff + 18432);
            uint32_t bl1 = *(const uint32_t*)(sm + boff + 18432 + 16);
            mma16816(acc[nf], ah, bh0, bh1);
            mma16816(acc[nf], al, bh0, bh1);
            mma16816(acc[nf], ah, bl0, bl1);
        }
    }

    const float* bs = (const float*)(sm + HG_BIAS);
    int rgA = row0 + w * 16 + lr;
#pragma unroll
    for (int nf = 0; nf < 16; nf++) {
        float b0 = bs[nf * 8 + lc], b1 = bs[nf * 8 + lc + 1];
        size_t cA = (size_t)rgA * 512 + col0 + nf * 8 + lc;
        *(float2*)&g_xg[cA] = make_float2(acc[nf][0] + b0, acc[nf][1] + b1);
        *(float2*)&g_xg[cA + 8 * 512] = make_float2(acc[nf][2] + b0, acc[nf][3] + b1);
    }
}

// ---------------- persistent LSTM: combined-B HMMA, 1 bar/step ----------------
// 120 CTAs x 256 threads (8 warps). Warp w, m-frags mf = gate: rows mf*128 + w*16.
// B = [h_hi seqs 0-3 | h_lo seqs 0-3] (16k x 8n per kf). Two mma per (mf,kf):
// Whi@B + Wlo@B, accumulated. Column c + column c+4 summed via shfl_xor(2)
// gives all four split products. Each lane then owns 2 complete cells.
// smem:
#define L4_WLO 0                       // WhhLo padded: 512 rows x 272 B = 139264
#define L4_XB  139264                  // xg double buf: 2 x 4x520 floats = 16640
#define L4_HB  155904                  // B double buf: 2 x 8 cols x 272 B = 4352
#define L4_HF  160256                  // h fp32 [128][4] = 2048
#define L4_TOTAL 162304

__global__ void __launch_bounds__(256) lstm4_kernel(
    const float* __restrict__ Wfc, const float* __restrict__ bfc,
    float* __restrict__ out)
{
    extern __shared__ char sm[];
    int tid = threadIdx.x, w = tid >> 5, l = tid & 31;
    int s0 = blockIdx.x * 4;
    uint32_t smb = smem_u32(sm);

    // stage WhhLo into 272-B padded rows
    {
        const uint32_t* wlo = (const uint32_t*)g_WhhLo;  // [512][64] u32
        for (int i = tid; i < 512 * 64; i += 256) {
            int row = i >> 6, cp = i & 63;
            *(uint32_t*)(sm + L4_WLO + row * 272 + cp * 4) = wlo[row * 64 + cp];
        }
    }
    // zero h (B) buffers
    for (int i = tid; i < 4352 / 4; i += 256) ((uint32_t*)(sm + L4_HB))[i] = 0;
    // preload xb t=0 (buffer 0)
    const float4* xg4 = (const float4*)g_xg;
    for (int i = tid; i < 512; i += 256) {
        int s = i >> 7, g4i = i & 127;
        *(float4*)(sm + L4_XB + (s * 520 + g4i * 4) * 4) = xg4[(size_t)(s0 + s) * 128 + g4i];
    }

    // WhhHi fragments -> registers: WH[gate][kf][4], rows gate*128 + w*16
    uint32_t WH[4][8][4];
    {
        const uint32_t* whi = (const uint32_t*)g_WhhHi;  // [512][64] u32
        int lr = l >> 2, lc = l & 3;
#pragma unroll
        for (int mf = 0; mf < 4; mf++)
#pragma unroll
            for (int kf = 0; kf < 8; kf++) {
                int row = mf * 128 + w * 16 + lr;
                int kc = kf * 8 + lc;
                WH[mf][kf][0] = whi[row * 64 + kc];
                WH[mf][kf][1] = whi[(row + 8) * 64 + kc];
                WH[mf][kf][2] = whi[row * 64 + kc + 4];
                WH[mf][kf][3] = whi[(row + 8) * 64 + kc + 4];
            }
    }
    __syncthreads();

    // ldmatrix lane base for WhhLo A-frags (mf stride 128*272)
    int lm = l >> 3, lr8 = l & 7;
    uint32_t wloBase = smb + L4_WLO
        + (uint32_t)((w * 16 + (lm & 1) * 8 + lr8) * 272 + ((lm >> 1) * 8) * 2);

    // register-resident Wlo for mf=0
    uint32_t WL0[8][4];
#pragma unroll
    for (int kf = 0; kf < 8; kf++) {
        asm volatile("ldmatrix.sync.aligned.m8n8.x4.shared.b16 {%0,%1,%2,%3}, [%4];"
            : "=r"(WL0[kf][0]), "=r"(WL0[kf][1]), "=r"(WL0[kf][2]), "=r"(WL0[kf][3])
            : "r"(wloBase + kf * 32));
    }

    // B-frag lane base (buffer 0)
    uint32_t hbA = smb + L4_HB + (uint32_t)((l >> 2) * 272 + (l & 3) * 4);

    // xb prefetch mapping
    int rC = tid & 127, sB = tid >> 7;

    // cell ownership: each lane owns (rL, sL) and (rL, sL+1)
    bool Alane = (l & 3) < 2;
    int rL = w * 16 + (l >> 2) + (Alane ? 0 : 8);
    int sL = ((l & 3) & 1) * 2;
    float cs0 = 0.f, cs1 = 0.f;

#pragma unroll 1
    for (int t = 0; t < TLEN; t++) {
        bool pf = (t + 1 < TLEN);
        float4 nx0, nx1;
        if (pf) {
            nx0 = xg4[(size_t)((t + 1) * NSEQ + s0 + sB) * 128 + rC];
            nx1 = xg4[(size_t)((t + 1) * NSEQ + s0 + sB + 2) * 128 + rC];
        }

        uint32_t hcur = hbA + (t & 1) * 2176;
        float acc[4][4];
#pragma unroll
        for (int mf = 0; mf < 4; mf++) {
            acc[mf][0] = 0.f; acc[mf][1] = 0.f; acc[mf][2] = 0.f; acc[mf][3] = 0.f;
        }

#pragma unroll
        for (int kf = 0; kf < 8; kf++) {
            uint32_t bh0, bh1;
            uint32_t ka = hcur + kf * 32;
            asm volatile("ld.shared.b32 %0, [%1];" : "=r"(bh0) : "r"(ka));
            asm volatile("ld.shared.b32 %0, [%1];" : "=r"(bh1) : "r"(ka + 16));
            // mf = 0: both W halves in registers
            mma16816(acc[0], WH[0][kf], bh0, bh1);
            mma16816(acc[0], WL0[kf], bh0, bh1);
#pragma unroll
            for (int mf = 1; mf < 4; mf++) {
                uint32_t wl0, wl1, wl2, wl3;
                uint32_t la = wloBase + mf * (128 * 272) + kf * 32;
                asm volatile("ldmatrix.sync.aligned.m8n8.x4.shared.b16 {%0,%1,%2,%3}, [%4];"
                    : "=r"(wl0), "=r"(wl1), "=r"(wl2), "=r"(wl3) : "r"(la));
                uint32_t wl[4] = {wl0, wl1, wl2, wl3};
                mma16816(acc[mf], WH[mf][kf], bh0, bh1);
                mma16816(acc[mf], wl, bh0, bh1);
            }
        }

        // store next xb buffer
        if (pf) {
            float* xd = (float*)(sm + L4_XB + ((t + 1) & 1) * 8320);
            *(float4*)&xd[sB * 520 + rC * 4] = nx0;
            *(float4*)&xd[(sB + 2) * 520 + rC * 4] = nx1;
        }

        // half-column sums via shfl_xor(2): lane gets its 2 complete cells
        float g0[4], g1[4];
#pragma unroll
        for (int mf = 0; mf < 4; mf++) {
            float sa = Alane ? acc[mf][2] : acc[mf][0];
            float ra = __shfl_xor_sync(0xffffffffu, sa, 2);
            float sb2 = Alane ? acc[mf][3] : acc[mf][1];
            float rb = __shfl_xor_sync(0xffffffffu, sb2, 2);
            g0[mf] = (Alane ? acc[mf][0] : acc[mf][2]) + ra;
            g1[mf] = (Alane ? acc[mf][1] : acc[mf][3]) + rb;
        }

        // activations: 2 cells per lane
        {
            const float* xbc = (const float*)(sm + L4_XB + (t & 1) * 8320);
            char* hn = sm + L4_HB + ((t + 1) & 1) * 2176;
            float* hf = (float*)(sm + L4_HF);

            // cell 0: (rL, sL)
            {
                float gi = g0[0] + xbc[sL * 520 + rL];
                float gf = g0[1] + xbc[sL * 520 + 128 + rL];
                float gg = g0[2] + xbc[sL * 520 + 256 + rL];
                float go = g0[3] + xbc[sL * 520 + 384 + rL];
                float i_ = 0.5f * tanh_t(0.5f * gi) + 0.5f;
                float f_ = 0.5f * tanh_t(0.5f * gf) + 0.5f;
                float o_ = 0.5f * tanh_t(0.5f * go) + 0.5f;
                float g_ = tanh_t(gg);
                cs0 = f_ * cs0 + i_ * g_;
                float h = o_ * tanh_t(cs0);
                __nv_bfloat16 hi = __float2bfloat16(h);
                float lo = h - __bfloat162float(hi);
                *(__nv_bfloat16*)(hn + sL * 272 + rL * 2) = hi;
                *(__nv_bfloat16*)(hn + (4 + sL) * 272 + rL * 2) = __float2bfloat16(lo);
                if (t == TLEN - 1) hf[rL * 4 + sL] = h;
            }
            // cell 1: (rL, sL+1)
            {
                int s1 = sL + 1;
                float gi = g1[0] + xbc[s1 * 520 + rL];
                float gf = g1[1] + xbc[s1 * 520 + 128 + rL];
                float gg = g1[2] + xbc[s1 * 520 + 256 + rL];
                float go = g1[3] + xbc[s1 * 520 + 384 + rL];
                float i_ = 0.5f * tanh_t(0.5f * gi) + 0.5f;
                float f_ = 0.5f * tanh_t(0.5f * gf) + 0.5f;
                float o_ = 0.5f * tanh_t(0.5f * go) + 0.5f;
                float g_ = tanh_t(gg);
                cs1 = f_ * cs1 + i_ * g_;
                float h = o_ * tanh_t(cs1);
                __nv_bfloat16 hi = __float2bfloat16(h);
                float lo = h - __bfloat162float(hi);
                *(__nv_bfloat16*)(hn + s1 * 272 + rL * 2) = hi;
                *(__nv_bfloat16*)(hn + (4 + s1) * 272 + rL * 2) = __float2bfloat16(lo);
                if (t == TLEN - 1) hf[rL * 4 + s1] = h;
            }
        }
        __syncthreads();
    }

    // ---- FC epilogue: reuse WLO region for W_fc^T ----
    float* wfs = (float*)sm;
    for (int idx = tid; idx < CH * HID; idx += 256) {
        int c = idx >> 7, j = idx & 127;
        wfs[j * 64 + c] = Wfc[idx];
    }
    __syncthreads();
    {
        int c = tid & 63, s = tid >> 6;
        float accf = bfc[c];
        const float* hf = (const float*)(sm + L4_HF);
#pragma unroll 8
        for (int j = 0; j < HID; j++)
            accf += hf[j * 4 + s] * wfs[j * 64 + c];
        out[(s0 + s) * 64 + c] = accf;
    }
}

// ---------------- launch ----------------
extern "C" void kernel_launch(void* const* d_in, const int* in_sizes, int n_in,
                              void* d_out, int out_size)
{
    const float* x   = (const float*)d_in[0];
    const float* Wih = (const float*)d_in[1];
    const float* Whh = (const float*)d_in[2];
    const float* bih = (const float*)d_in[3];
    const float* bhh = (const float*)d_in[4];
    const float* Wfc = (const float*)d_in[5];
    const float* bfc = (const float*)d_in[6];
    float* out = (float*)d_out;

    cudaFuncSetAttribute(hgemm_kernel, cudaFuncAttributeMaxDynamicSharedMemorySize, HG_SMEM);
    cudaFuncSetAttribute(lstm4_kernel, cudaFuncAttributeMaxDynamicSharedMemorySize, L4_TOTAL);

    prep_kernel<<<256, 256>>>(Wih, Whh, bih, bhh);
    transp_kernel<<<dim3(TLEN, 16), 256>>>(x);
    hgemm_kernel<<<dim3(NROW / 128, 4), 256, HG_SMEM>>>();
    lstm4_kernel<<<120, 256, L4_TOTAL>>>(Wfc, bfc, out);
}